// round 11
// baseline (speedup 1.0000x reference)
#include <cuda_runtime.h>
#include <cuda_bf16.h>
#include <cstdint>
#include <math.h>

// ============================================================================
// Equiformer FFN, warp mma.sync m16n8k16 bf16 hi/lo 3-term split, fp32 acc.
// CTA = 64 nodes, 256 threads (8 warps 2m x 4n), 2 CTAs/SM. Weights pre-split
// (tiny prep); X converted in-kernel via CONTIGUOUS float4 loads (component
// extraction in registers). B fragments loaded pairwise with ldmatrix.x4.
// ============================================================================

#define THREADS 256
#define MAXCTA  1563

// ---- pre-split weights ----
#define OFF10 0        // [672 n][136]   (7 chunks of 96 n)
#define OFF11 91392    // [192 n][72]    (2 chunks of 96 n)
#define OFF12 105216   // [96 n][40]
#define OFF20 109056   // 8 x [128 n][56]   (K chunks of 48)
#define OFF21 166400   // 2 x [64 n][104]   (K chunks of 96)
#define OFF22 179712   // [32 n][104]
#define WTOT  183040
__device__ __align__(16) uint16_t g_wh[WTOT];
__device__ __align__(16) uint16_t g_wl[WTOT];

// ---- scalars hi/lo [64 r][392] + gates fp32 [64 r][288] ----
__device__ __align__(16) uint16_t g_scH[(size_t)MAXCTA * 25088];
__device__ __align__(16) uint16_t g_scL[(size_t)MAXCTA * 25088];
__device__ __align__(16) float    g_gate[(size_t)MAXCTA * 18432];

#define SM_TOT 100352

__device__ __forceinline__ uint32_t s2u(const void* p) {
    uint32_t a;
    asm("{ .reg .u64 t; cvta.to.shared.u64 t, %1; cvt.u32.u64 %0, t; }" : "=r"(a) : "l"(p));
    return a;
}
__device__ __forceinline__ void ldm_x4(uint32_t d[4], uint32_t a) {
    asm volatile("ldmatrix.sync.aligned.m8n8.x4.shared.b16 {%0,%1,%2,%3}, [%4];"
                 : "=r"(d[0]), "=r"(d[1]), "=r"(d[2]), "=r"(d[3]) : "r"(a));
}
__device__ __forceinline__ void ldm_x2(uint32_t d[2], uint32_t a) {
    asm volatile("ldmatrix.sync.aligned.m8n8.x2.shared.b16 {%0,%1}, [%2];"
                 : "=r"(d[0]), "=r"(d[1]) : "r"(a));
}
__device__ __forceinline__ void mma_bf(float (&c)[4], const uint32_t* a,
                                       const uint32_t* b) {
    asm volatile("mma.sync.aligned.m16n8k16.row.col.f32.bf16.bf16.f32 "
                 "{%0,%1,%2,%3},{%4,%5,%6,%7},{%8,%9},{%0,%1,%2,%3};"
                 : "+f"(c[0]), "+f"(c[1]), "+f"(c[2]), "+f"(c[3])
                 : "r"(a[0]), "r"(a[1]), "r"(a[2]), "r"(a[3]), "r"(b[0]), "r"(b[1]));
}
__device__ __forceinline__ void split(float v, uint16_t& h, uint16_t& l) {
    const __nv_bfloat16 hb = __float2bfloat16_rn(v);
    h = __bfloat16_as_ushort(hb);
    l = __bfloat16_as_ushort(__float2bfloat16_rn(v - __bfloat162float(hb)));
}
__device__ __forceinline__ void st_pair(uint16_t* bH, uint16_t* bL, int idx,
                                        float v0, float v1) {
    uint16_t h0, l0, h1, l1;
    split(v0, h0, l0);
    split(v1, h1, l1);
    *reinterpret_cast<uint32_t*>(bH + idx) = (uint32_t)h0 | ((uint32_t)h1 << 16);
    *reinterpret_cast<uint32_t*>(bL + idx) = (uint32_t)l0 | ((uint32_t)l1 << 16);
}
__device__ __forceinline__ void cp16(uint32_t dst, const void* src) {
    asm volatile("cp.async.cg.shared.global [%0], [%1], 16;" :: "r"(dst), "l"(src));
}
#define CP_COMMIT() asm volatile("cp.async.commit_group;" ::: "memory")
#define CP_WAIT0()  asm volatile("cp.async.wait_group 0;" ::: "memory")
#define CP_WAIT1()  asm volatile("cp.async.wait_group 1;" ::: "memory")

__device__ __forceinline__ void cpy2(uint32_t dH, uint32_t dL,
                                     const uint16_t* sH, const uint16_t* sL, int elems) {
    const int n16 = elems >> 3;
    for (int i = threadIdx.x; i < n16; i += THREADS) {
        cp16(dH + i * 16, sH + i * 8);
        cp16(dL + i * 16, sL + i * 8);
    }
}
__device__ __forceinline__ void cpy_sc48(uint32_t dH, uint32_t dL,
                                         const uint16_t* sH, const uint16_t* sL,
                                         int kcOff) {
    for (int i = threadIdx.x; i < 384; i += THREADS) {
        const int r = i / 6, ch = i - r * 6;
        const uint32_t d = r * 112 + ch * 16;
        const int s = r * 392 + kcOff + ch * 8;
        cp16(dH + d, sH + s);
        cp16(dL + d, sL + s);
    }
}

// ---- X conversion (coalesced contiguous loads, register extraction) ----
__device__ __forceinline__ void pack_sts8(const float* v, uint32_t dH, uint32_t dL) {
    uint32_t hi[4], lo[4];
#pragma unroll
    for (int q = 0; q < 4; q++) {
        uint16_t h0, l0, h1, l1;
        split(v[2 * q], h0, l0);
        split(v[2 * q + 1], h1, l1);
        hi[q] = (uint32_t)h0 | ((uint32_t)h1 << 16);
        lo[q] = (uint32_t)l0 | ((uint32_t)l1 << 16);
    }
    asm volatile("st.shared.v4.b32 [%0], {%1,%2,%3,%4};"
                 :: "r"(dH), "r"(hi[0]), "r"(hi[1]), "r"(hi[2]), "r"(hi[3]) : "memory");
    asm volatile("st.shared.v4.b32 [%0], {%1,%2,%3,%4};"
                 :: "r"(dL), "r"(lo[0]), "r"(lo[1]), "r"(lo[2]), "r"(lo[3]) : "memory");
}
__device__ __forceinline__ void pack_sts4(float v0, float v1, float v2, float v3,
                                          uint32_t dH, uint32_t dL) {
    uint16_t h0, l0, h1, l1, h2, l2, h3, l3;
    split(v0, h0, l0);
    split(v1, h1, l1);
    split(v2, h2, l2);
    split(v3, h3, l3);
    const uint32_t hi0 = (uint32_t)h0 | ((uint32_t)h1 << 16);
    const uint32_t hi1 = (uint32_t)h2 | ((uint32_t)h3 << 16);
    const uint32_t lo0 = (uint32_t)l0 | ((uint32_t)l1 << 16);
    const uint32_t lo1 = (uint32_t)l2 | ((uint32_t)l3 << 16);
    asm volatile("st.shared.v2.b32 [%0], {%1,%2};" :: "r"(dH), "r"(hi0), "r"(hi1) : "memory");
    asm volatile("st.shared.v2.b32 [%0], {%1,%2};" :: "r"(dL), "r"(lo0), "r"(lo1) : "memory");
}
// l=0 block: contiguous cols 0..127 -> [64 r][136 pad]
__device__ void conv_seg0(uint32_t dH, uint32_t dL, const float* __restrict__ X,
                          int nbase, int Nn) {
    for (int idx = threadIdx.x; idx < 1024; idx += THREADS) {
        const int r = idx >> 4, k8 = idx & 15;
        const float4* p = reinterpret_cast<const float4*>(
            X + (size_t)min(nbase + r, Nn - 1) * 480 + k8 * 8);
        const float4 a = __ldg(&p[0]), b = __ldg(&p[1]);
        const float v[8] = {a.x, a.y, a.z, a.w, b.x, b.y, b.z, b.w};
        pack_sts8(v, dH + r * 272 + k8 * 16, dL + r * 272 + k8 * 16);
    }
}
// l=1 component I: cols 128+3k+I, k in [0,64) -> [64 r][72 kpad] (rowB=144)
template <int I>
__device__ void conv1(uint32_t dH, uint32_t dL, const float* __restrict__ X,
                      int nbase, int Nn) {
    for (int idx = threadIdx.x; idx < 512; idx += THREADS) {
        const int r = idx >> 3, b = idx & 7;
        const float* p = X + (size_t)min(nbase + r, Nn - 1) * 480 + 128 + 24 * b;
        const float4* p4 = reinterpret_cast<const float4*>(p);
        {   // half 0: k = 8b+0..3 -> f[I + 3q], q=0..3 within f[0..11]
            const float4 f0 = __ldg(&p4[0]), f1 = __ldg(&p4[1]), f2 = __ldg(&p4[2]);
            const float f[12] = {f0.x, f0.y, f0.z, f0.w, f1.x, f1.y, f1.z, f1.w,
                                 f2.x, f2.y, f2.z, f2.w};
            pack_sts4(f[I], f[I + 3], f[I + 6], f[I + 9],
                      dH + r * 144 + b * 16, dL + r * 144 + b * 16);
        }
        {   // half 1: k = 8b+4..7 -> f[I + 3q] within f[12..23]
            const float4 f0 = __ldg(&p4[3]), f1 = __ldg(&p4[4]), f2 = __ldg(&p4[5]);
            const float f[12] = {f0.x, f0.y, f0.z, f0.w, f1.x, f1.y, f1.z, f1.w,
                                 f2.x, f2.y, f2.z, f2.w};
            pack_sts4(f[I], f[I + 3], f[I + 6], f[I + 9],
                      dH + r * 144 + b * 16 + 8, dL + r * 144 + b * 16 + 8);
        }
    }
}
// l=2 component I: cols 320+5k+I, k in [0,32) -> [64 r][40 kpad] (rowB=80)
template <int I>
__device__ void conv2(uint32_t dH, uint32_t dL, const float* __restrict__ X,
                      int nbase, int Nn) {
    for (int idx = threadIdx.x; idx < 256; idx += THREADS) {
        const int r = idx >> 2, b = idx & 3;
        const float* p = X + (size_t)min(nbase + r, Nn - 1) * 480 + 320 + 40 * b;
        const float4* p4 = reinterpret_cast<const float4*>(p);
#pragma unroll
        for (int h = 0; h < 2; h++) {   // halves: k = 8b + 4h + 0..3
            const float4 f0 = __ldg(&p4[5 * h + 0]), f1 = __ldg(&p4[5 * h + 1]),
                         f2 = __ldg(&p4[5 * h + 2]), f3 = __ldg(&p4[5 * h + 3]),
                         f4 = __ldg(&p4[5 * h + 4]);
            const float f[20] = {f0.x, f0.y, f0.z, f0.w, f1.x, f1.y, f1.z, f1.w,
                                 f2.x, f2.y, f2.z, f2.w, f3.x, f3.y, f3.z, f3.w,
                                 f4.x, f4.y, f4.z, f4.w};
            pack_sts4(f[I], f[I + 5], f[I + 10], f[I + 15],
                      dH + r * 80 + b * 16 + 8 * h, dL + r * 80 + b * 16 + 8 * h);
        }
    }
}

template <int NTW>
__device__ __forceinline__ void zacc(float (&acc)[2][NTW][4]) {
#pragma unroll
    for (int m = 0; m < 2; m++)
#pragma unroll
        for (int j = 0; j < NTW; j++)
#pragma unroll
            for (int q = 0; q < 4; q++) acc[m][j][q] = 0.0f;
}

template <int KT, int NTW>
__device__ __forceinline__ void mma_tile(uint32_t uAH, uint32_t uAL, uint32_t uBH,
                                         uint32_t uBL, int Kpad, int rowBase, int n8Base,
                                         int lane, float (&acc)[2][NTW][4]) {
    const int ar  = rowBase + (lane & 15);
    const int ak8 = (lane >> 4) * 8;
    // x4 B addressing (pair of n8 tiles)
    const int q4  = lane >> 3;
    const int jj  = q4 >> 1;
    const int kk8 = (q4 & 1) * 8;
    const int brow = lane & 7;
    // x2 B addressing (odd tail)
    const int bn  = lane & 7;
    const int bk8 = ((lane >> 3) & 1) * 8;
#pragma unroll 1
    for (int kt = 0; kt < KT; kt++) {
        const int kb = kt * 16;
        uint32_t Ah[2][4], Al[2][4];
#pragma unroll
        for (int m = 0; m < 2; m++) {
            const uint32_t off = (uint32_t)(((ar + m * 16) * Kpad + kb + ak8) * 2);
            ldm_x4(Ah[m], uAH + off);
            ldm_x4(Al[m], uAL + off);
        }
#pragma unroll
        for (int j = 0; j + 1 < NTW; j += 2) {
            const uint32_t boff = (uint32_t)(
                (((n8Base + j + jj) * 8 + brow) * Kpad + kb + kk8) * 2);
            uint32_t Bh[4], Bl[4];
            ldm_x4(Bh, uBH + boff);
            ldm_x4(Bl, uBL + boff);
#pragma unroll
            for (int m = 0; m < 2; m++) {
                mma_bf(acc[m][j], Ah[m], Bh);
                mma_bf(acc[m][j], Ah[m], Bl);
                mma_bf(acc[m][j], Al[m], Bh);
                mma_bf(acc[m][j + 1], Ah[m], Bh + 2);
                mma_bf(acc[m][j + 1], Ah[m], Bl + 2);
                mma_bf(acc[m][j + 1], Al[m], Bh + 2);
            }
        }
        if (NTW & 1) {
            const int j = NTW - 1;
            const uint32_t boff =
                (uint32_t)((((n8Base + j) * 8 + bn) * Kpad + kb + bk8) * 2);
            uint32_t Bh[2], Bl[2];
            ldm_x2(Bh, uBH + boff);
            ldm_x2(Bl, uBL + boff);
#pragma unroll
            for (int m = 0; m < 2; m++) {
                mma_bf(acc[m][j], Ah[m], Bh);
                mma_bf(acc[m][j], Ah[m], Bl);
                mma_bf(acc[m][j], Al[m], Bh);
            }
        }
    }
}

// ---- prep: weights only ----
__device__ __forceinline__ void prep_w(const float* __restrict__ W, int K, int N,
                                       int Kpad, int base) {
    const int tot = K * N;
    for (int idx = blockIdx.x * blockDim.x + threadIdx.x; idx < tot;
         idx += gridDim.x * blockDim.x) {
        const int k = idx / N, n = idx - k * N;
        uint16_t h, l;
        split(__ldg(&W[idx]), h, l);
        g_wh[base + n * Kpad + k] = h;
        g_wl[base + n * Kpad + k] = l;
    }
}
__global__ void prep(const float* W1_0, const float* W1_1, const float* W1_2,
                     const float* W2_0, const float* W2_1, const float* W2_2) {
    prep_w(W1_0, 128, 672, 136, OFF10);
    prep_w(W1_1, 64, 192, 72, OFF11);
    prep_w(W1_2, 32, 96, 40, OFF12);
    for (int idx = blockIdx.x * blockDim.x + threadIdx.x; idx < 384 * 128;
         idx += gridDim.x * blockDim.x) {
        const int k = idx / 128, n = idx - k * 128;
        const int kc = k / 48, kk = k - kc * 48;
        uint16_t h, l;
        split(__ldg(&W2_0[idx]), h, l);
        g_wh[OFF20 + kc * 7168 + n * 56 + kk] = h;
        g_wl[OFF20 + kc * 7168 + n * 56 + kk] = l;
    }
    for (int idx = blockIdx.x * blockDim.x + threadIdx.x; idx < 192 * 64;
         idx += gridDim.x * blockDim.x) {
        const int k = idx / 64, n = idx - k * 64;
        const int kc = k / 96, kk = k - kc * 96;
        uint16_t h, l;
        split(__ldg(&W2_1[idx]), h, l);
        g_wh[OFF21 + kc * 6656 + n * 104 + kk] = h;
        g_wl[OFF21 + kc * 6656 + n * 104 + kk] = l;
    }
    prep_w(W2_2, 96, 32, 104, OFF22);
}

__global__ void __launch_bounds__(THREADS, 2)
ffn_main(const float* __restrict__ X, const float* __restrict__ attr,
         const float* __restrict__ b1, const float* __restrict__ b2,
         float* __restrict__ out, int Nn) {
    extern __shared__ char smem[];
    float* sAttr = (float*)smem;
    const uint32_t sb = s2u(smem);
    const int tid = threadIdx.x, lane = tid & 31, w = tid >> 5;
    const int g = lane >> 2, t2 = lane & 3;
    const int mt = w >> 2, nt = w & 3;   // 2m x 4n
    const size_t cta = blockIdx.x;
    const int nbase = (int)cta * 64;
    uint16_t* scH = g_scH + cta * 25088;
    uint16_t* scL = g_scL + cta * 25088;
    float* gate = g_gate + cta * 18432;

    const float I10 = 0.08838834764831843f, I11 = 0.125f, I12 = 0.17677669529663687f;
    const float I20 = 0.05103103630798288f, I21 = 0.07216878364870323f,
                I22 = 0.10206207261596577f;

    // ===== P0: h0 = x0 @ W1_0 (7 N-chunks of 96) =====
    cpy2(sb + 35328, sb + 61440, g_wh + OFF10, g_wl + OFF10, 13056);
    CP_COMMIT();
    if (tid < 64) sAttr[tid] = attr[min(nbase + tid, Nn - 1)];
    conv_seg0(sb + 512, sb + 17920, X, nbase, Nn);
    for (int ch = 0; ch < 7; ch++) {
        CP_WAIT0();
        __syncthreads();
        float acc[2][3][4];
        zacc<3>(acc);
        mma_tile<8, 3>(sb + 512, sb + 17920, sb + 35328, sb + 61440, 136,
                       mt * 32, nt * 3, lane, acc);
        __syncthreads();
        if (ch < 6) {
            cpy2(sb + 35328, sb + 61440, g_wh + OFF10 + (ch + 1) * 13056,
                 g_wl + OFF10 + (ch + 1) * 13056, 13056);
            CP_COMMIT();
        } else {
            cpy_sc48(sb + 512, sb + 7680, scH, scL, 0);
            cpy2(sb + 29184, sb + 43520, g_wh + OFF20, g_wl + OFF20, 7168);
            CP_COMMIT();
        }
#pragma unroll
        for (int m = 0; m < 2; m++) {
            const int r0 = mt * 32 + m * 16 + g;
#pragma unroll
            for (int j = 0; j < 3; j++) {
                const int gc = ch * 96 + (nt * 3 + j) * 8 + t2 * 2;
                const float bb0 = __ldg(&b1[gc]), bb1 = __ldg(&b1[gc + 1]);
#pragma unroll
                for (int h2 = 0; h2 < 2; h2++) {
                    const int r = r0 + h2 * 8;
                    const float a = sAttr[r] * I10;
                    float x0 = acc[m][j][h2 * 2] * a + bb0;
                    float x1 = acc[m][j][h2 * 2 + 1] * a + bb1;
                    const float s0 = 1.0f / (1.0f + __expf(-x0));
                    const float s1 = 1.0f / (1.0f + __expf(-x1));
                    if (gc < 384) {
                        st_pair(scH, scL, r * 392 + gc, x0 * s0, x1 * s1);
                    } else {
                        *reinterpret_cast<float2*>(gate + r * 288 + gc - 384) =
                            make_float2(s0, s1);
                    }
                }
            }
        }
        if (ch == 6) __syncthreads();
    }

    // ===== P1: out0 = scalars @ W2_0 (8 K-chunks of 48, double-buffered) =====
    {
        const uint32_t aH[2] = {sb + 512, sb + 14848};
        const uint32_t aL[2] = {sb + 7680, sb + 22016};
        const uint32_t bH[2] = {sb + 29184, sb + 57856};
        const uint32_t bL[2] = {sb + 43520, sb + 72192};
        float acc[2][4][4];
        zacc<4>(acc);
        for (int kc = 0; kc < 8; kc++) {
            const int s = kc & 1;
            if (kc < 7) {
                cpy_sc48(aH[1 - s], aL[1 - s], scH, scL, (kc + 1) * 48);
                cpy2(bH[1 - s], bL[1 - s], g_wh + OFF20 + (kc + 1) * 7168,
                     g_wl + OFF20 + (kc + 1) * 7168, 7168);
                CP_COMMIT();
                CP_WAIT1();
            } else {
                CP_WAIT0();
            }
            __syncthreads();
            mma_tile<3, 4>(aH[s], aL[s], bH[s], bL[s], 56, mt * 32, nt * 4, lane, acc);
            __syncthreads();
        }
        cpy2(sb + 18944, sb + 32768, g_wh + OFF11, g_wl + OFF11, 6912);
        CP_COMMIT();
        conv1<0>(sb + 512, sb + 9728, X, nbase, Nn);
#pragma unroll
        for (int m = 0; m < 2; m++) {
            const int r0 = mt * 32 + m * 16 + g;
#pragma unroll
            for (int j = 0; j < 4; j++) {
                const int c = (nt * 4 + j) * 8 + t2 * 2;
                const float bb0 = __ldg(&b2[c]), bb1 = __ldg(&b2[c + 1]);
#pragma unroll
                for (int h2 = 0; h2 < 2; h2++) {
                    const int r = r0 + h2 * 8, node = nbase + r;
                    if (node < Nn) {
                        const float a = sAttr[r] * I20;
                        *reinterpret_cast<float2*>(out + (size_t)node * 480 + c) =
                            make_float2(acc[m][j][h2 * 2] * a + bb0,
                                        acc[m][j][h2 * 2 + 1] * a + bb1);
                    }
                }
            }
        }
    }

    // ===== P2: mid1_i -> out1_i fused, K-split 96+96 (i=0..2) =====
    {
        uint16_t* mH = (uint16_t*)(smem + 46592);
        uint16_t* mL = (uint16_t*)(smem + 59904);
        for (int i = 0; i < 3; i++) {
            float acc2[2][2][4];
            zacc<2>(acc2);
            for (int kc = 0; kc < 2; kc++) {
                CP_WAIT0();
                __syncthreads();
                float acc[2][3][4];
                zacc<3>(acc);
                mma_tile<4, 3>(sb + 512, sb + 9728, sb + 18944, sb + 32768, 72,
                               mt * 32, nt * 3, lane, acc);
                __syncthreads();
                cpy2(sb + 73216, sb + 86528, g_wh + OFF21 + kc * 6656,
                     g_wl + OFF21 + kc * 6656, 6656);
                if (kc == 0) {
                    cpy2(sb + 18944, sb + 32768, g_wh + OFF11 + 6912,
                         g_wl + OFF11 + 6912, 6912);
                } else if (i < 2) {
                    cpy2(sb + 18944, sb + 32768, g_wh + OFF11, g_wl + OFF11, 6912);
                } else {
                    cpy2(sb + 10752, sb + 18432, g_wh + OFF12, g_wl + OFF12, 3840);
                    cpy2(sb + 26112, sb + 32768, g_wh + OFF22, g_wl + OFF22, 3328);
                }
                CP_COMMIT();
#pragma unroll
                for (int m = 0; m < 2; m++) {
                    const int r0 = mt * 32 + m * 16 + g;
#pragma unroll
                    for (int j = 0; j < 3; j++) {
                        const int c = (nt * 3 + j) * 8 + t2 * 2;
#pragma unroll
                        for (int h2 = 0; h2 < 2; h2++) {
                            const int r = r0 + h2 * 8;
                            const float a = sAttr[r] * I11;
                            const float2 gg = *reinterpret_cast<const float2*>(
                                gate + r * 288 + kc * 96 + c);
                            st_pair(mH, mL, r * 104 + c,
                                    acc[m][j][h2 * 2] * a * gg.x,
                                    acc[m][j][h2 * 2 + 1] * a * gg.y);
                        }
                    }
                }
                if (kc == 1) {
                    if (i == 0)      conv1<1>(sb + 512, sb + 9728, X, nbase, Nn);
                    else if (i == 1) conv1<2>(sb + 512, sb + 9728, X, nbase, Nn);
                    else             conv2<0>(sb + 512, sb + 5632, X, nbase, Nn);
                }
                __syncthreads();
                CP_WAIT0();
                __syncthreads();
                mma_tile<6, 2>(sb + 46592, sb + 59904, sb + 73216, sb + 86528, 104,
                               mt * 32, nt * 2, lane, acc2);
                __syncthreads();
            }
#pragma unroll
            for (int m = 0; m < 2; m++) {
                const int r0 = mt * 32 + m * 16 + g;
#pragma unroll
                for (int j = 0; j < 2; j++) {
                    const int c = (nt * 2 + j) * 8 + t2 * 2;
#pragma unroll
                    for (int h2 = 0; h2 < 2; h2++) {
                        const int r = r0 + h2 * 8, node = nbase + r;
                        if (node < Nn) {
                            const float a = sAttr[r] * I21;
                            out[(size_t)node * 480 + 128 + c * 3 + i] =
                                acc2[m][j][h2 * 2] * a;
                            out[(size_t)node * 480 + 128 + (c + 1) * 3 + i] =
                                acc2[m][j][h2 * 2 + 1] * a;
                        }
                    }
                }
            }
        }
    }

    // ===== P3: mid2_i -> out2_i fused (i=0..4) =====
    {
        uint16_t* mH = (uint16_t*)(smem + 46592);
        uint16_t* mL = (uint16_t*)(smem + 59904);
        for (int i = 0; i < 5; i++) {
            CP_WAIT0();
            __syncthreads();
            float acc[2][3][4];
            zacc<3>(acc);
            mma_tile<2, 3>(sb + 512, sb + 5632, sb + 10752, sb + 18432, 40,
                           mt * 32, nt * 3, lane, acc);
            __syncthreads();
#pragma unroll
            for (int m = 0; m < 2; m++) {
                const int r0 = mt * 32 + m * 16 + g;
#pragma unroll
                for (int j = 0; j < 3; j++) {
                    const int c = (nt * 3 + j) * 8 + t2 * 2;
#pragma unroll
                    for (int h2 = 0; h2 < 2; h2++) {
                        const int r = r0 + h2 * 8;
                        const float a = sAttr[r] * I12;
                        const float2 gg = *reinterpret_cast<const float2*>(
                            gate + r * 288 + 192 + c);
                        st_pair(mH, mL, r * 104 + c, acc[m][j][h2 * 2] * a * gg.x,
                                acc[m][j][h2 * 2 + 1] * a * gg.y);
                    }
                }
            }
            if (i == 0)      conv2<1>(sb + 512, sb + 5632, X, nbase, Nn);
            else if (i == 1) conv2<2>(sb + 512, sb + 5632, X, nbase, Nn);
            else if (i == 2) conv2<3>(sb + 512, sb + 5632, X, nbase, Nn);
            else if (i == 3) conv2<4>(sb + 512, sb + 5632, X, nbase, Nn);
            __syncthreads();
            float acc2[2][1][4];
            zacc<1>(acc2);
            mma_tile<6, 1>(sb + 46592, sb + 59904, sb + 26112, sb + 32768, 104,
                           mt * 32, nt, lane, acc2);
            __syncthreads();
#pragma unroll
            for (int m = 0; m < 2; m++) {
                const int r0 = mt * 32 + m * 16 + g;
                const int c = nt * 8 + t2 * 2;
#pragma unroll
                for (int h2 = 0; h2 < 2; h2++) {
                    const int r = r0 + h2 * 8, node = nbase + r;
                    if (node < Nn) {
                        const float a = sAttr[r] * I22;
                        out[(size_t)node * 480 + 320 + c * 5 + i] =
                            acc2[m][0][h2 * 2] * a;
                        out[(size_t)node * 480 + 320 + (c + 1) * 5 + i] =
                            acc2[m][0][h2 * 2 + 1] * a;
                    }
                }
            }
        }
    }
}

extern "C" void kernel_launch(void* const* d_in, const int* in_sizes, int n_in,
                              void* d_out, int out_size) {
    const float* X    = (const float*)d_in[0];
    const float* attr = (const float*)d_in[1];
    const float* W1_0 = (const float*)d_in[2];
    const float* W1_1 = (const float*)d_in[3];
    const float* W1_2 = (const float*)d_in[4];
    const float* b1   = (const float*)d_in[5];
    const float* W2_0 = (const float*)d_in[6];
    const float* W2_1 = (const float*)d_in[7];
    const float* W2_2 = (const float*)d_in[8];
    const float* b2   = (const float*)d_in[9];
    float* out = (float*)d_out;

    const int N = in_sizes[0] / 480;
    int nct = (N + 63) / 64;
    if (nct > MAXCTA) nct = MAXCTA;

    prep<<<160, 256>>>(W1_0, W1_1, W1_2, W2_0, W2_1, W2_2);
    cudaFuncSetAttribute(ffn_main, cudaFuncAttributeMaxDynamicSharedMemorySize, SM_TOT);
    ffn_main<<<nct, THREADS, SM_TOT>>>(X, attr, b1, b2, out, N);
}

// round 13
// speedup vs baseline: 1.0127x; 1.0127x over previous
#include <cuda_runtime.h>
#include <cuda_bf16.h>
#include <cstdint>
#include <math.h>

// ============================================================================
// Equiformer FFN, warp mma.sync m16n8k16 bf16 hi/lo 3-term split, fp32 acc.
// CTA = 64 nodes, 256 threads (8 warps 2m x 4n). smem <= 68.5KB + regs <= 84
// => 3 CTAs/SM (24 warps). R13 = R12 + race/overlap fixes:
//   - P2: __syncthreads between out1 mma and W2_1 buffer overwrite commit
//   - P3: mid hi@26112 lo@39424 (13312B each), W2_2 @52736/59392
//   - P3 entry sync before W2_2 commit
// ============================================================================

#define THREADS 256
#define MAXCTA  1563

#define OFF10 0        // [672 n][136]
#define OFF11 91392    // [192 n][72]
#define OFF12 105216   // [96 n][40]
#define OFF20 109056   // 12 x [128 n][40]  (K chunks of 32)
#define OFF21 170496   // 4 x [64 n][56]    (K chunks of 48)
#define OFF22 184832   // [32 n][104]
#define WTOT  188160
__device__ __align__(16) uint16_t g_wh[WTOT];
__device__ __align__(16) uint16_t g_wl[WTOT];

__device__ __align__(16) uint16_t g_scH[(size_t)MAXCTA * 25088];
__device__ __align__(16) uint16_t g_scL[(size_t)MAXCTA * 25088];
__device__ __align__(16) float    g_gate[(size_t)MAXCTA * 18432];

#define SM_TOT 70144

__device__ __forceinline__ uint32_t s2u(const void* p) {
    uint32_t a;
    asm("{ .reg .u64 t; cvta.to.shared.u64 t, %1; cvt.u32.u64 %0, t; }" : "=r"(a) : "l"(p));
    return a;
}
__device__ __forceinline__ void ldm_x4(uint32_t d[4], uint32_t a) {
    asm volatile("ldmatrix.sync.aligned.m8n8.x4.shared.b16 {%0,%1,%2,%3}, [%4];"
                 : "=r"(d[0]), "=r"(d[1]), "=r"(d[2]), "=r"(d[3]) : "r"(a));
}
__device__ __forceinline__ void ldm_x2(uint32_t d[2], uint32_t a) {
    asm volatile("ldmatrix.sync.aligned.m8n8.x2.shared.b16 {%0,%1}, [%2];"
                 : "=r"(d[0]), "=r"(d[1]) : "r"(a));
}
__device__ __forceinline__ void mma_bf(float (&c)[4], const uint32_t (&a)[4],
                                       const uint32_t (&b)[2]) {
    asm volatile("mma.sync.aligned.m16n8k16.row.col.f32.bf16.bf16.f32 "
                 "{%0,%1,%2,%3},{%4,%5,%6,%7},{%8,%9},{%0,%1,%2,%3};"
                 : "+f"(c[0]), "+f"(c[1]), "+f"(c[2]), "+f"(c[3])
                 : "r"(a[0]), "r"(a[1]), "r"(a[2]), "r"(a[3]), "r"(b[0]), "r"(b[1]));
}
__device__ __forceinline__ void split(float v, uint16_t& h, uint16_t& l) {
    const __nv_bfloat16 hb = __float2bfloat16_rn(v);
    h = __bfloat16_as_ushort(hb);
    l = __bfloat16_as_ushort(__float2bfloat16_rn(v - __bfloat162float(hb)));
}
__device__ __forceinline__ void st_pair(uint16_t* bH, uint16_t* bL, int idx,
                                        float v0, float v1) {
    uint16_t h0, l0, h1, l1;
    split(v0, h0, l0);
    split(v1, h1, l1);
    *reinterpret_cast<uint32_t*>(bH + idx) = (uint32_t)h0 | ((uint32_t)h1 << 16);
    *reinterpret_cast<uint32_t*>(bL + idx) = (uint32_t)l0 | ((uint32_t)l1 << 16);
}
__device__ __forceinline__ void cp16(uint32_t dst, const void* src) {
    asm volatile("cp.async.cg.shared.global [%0], [%1], 16;" :: "r"(dst), "l"(src));
}
#define CP_COMMIT() asm volatile("cp.async.commit_group;" ::: "memory")
#define CP_WAIT0()  asm volatile("cp.async.wait_group 0;" ::: "memory")
#define CP_WAIT1()  asm volatile("cp.async.wait_group 1;" ::: "memory")

__device__ __forceinline__ void cpy2(uint32_t dH, uint32_t dL,
                                     const uint16_t* sH, const uint16_t* sL, int elems) {
    const int n16 = elems >> 3;
    for (int i = threadIdx.x; i < n16; i += THREADS) {
        cp16(dH + i * 16, sH + i * 8);
        cp16(dL + i * 16, sL + i * 8);
    }
}
__device__ __forceinline__ void cpy_sc32(uint32_t dH, uint32_t dL,
                                         const uint16_t* sH, const uint16_t* sL,
                                         int kcOff) {
    const int i = threadIdx.x;
    if (i < 256) {
        const int r = i >> 2, ch = i & 3;
        const uint32_t d = r * 80 + ch * 16;
        const int s = r * 392 + kcOff + ch * 8;
        cp16(dH + d, sH + s);
        cp16(dL + d, sL + s);
    }
}

__device__ __forceinline__ void pack_sts8(const float* v, uint32_t dH, uint32_t dL) {
    uint32_t hi[4], lo[4];
#pragma unroll
    for (int q = 0; q < 4; q++) {
        uint16_t h0, l0, h1, l1;
        split(v[2 * q], h0, l0);
        split(v[2 * q + 1], h1, l1);
        hi[q] = (uint32_t)h0 | ((uint32_t)h1 << 16);
        lo[q] = (uint32_t)l0 | ((uint32_t)l1 << 16);
    }
    asm volatile("st.shared.v4.b32 [%0], {%1,%2,%3,%4};"
                 :: "r"(dH), "r"(hi[0]), "r"(hi[1]), "r"(hi[2]), "r"(hi[3]) : "memory");
    asm volatile("st.shared.v4.b32 [%0], {%1,%2,%3,%4};"
                 :: "r"(dL), "r"(lo[0]), "r"(lo[1]), "r"(lo[2]), "r"(lo[3]) : "memory");
}
__device__ void conv_seg0(uint32_t dH, uint32_t dL, const float* __restrict__ X,
                          int nbase, int Nn) {
    for (int idx = threadIdx.x; idx < 1024; idx += THREADS) {
        const int r = idx >> 4, k8 = idx & 15;
        const float4* p = reinterpret_cast<const float4*>(
            X + (size_t)min(nbase + r, Nn - 1) * 480 + k8 * 8);
        const float4 a = __ldg(&p[0]), b = __ldg(&p[1]);
        const float v[8] = {a.x, a.y, a.z, a.w, b.x, b.y, b.z, b.w};
        pack_sts8(v, dH + r * 272 + k8 * 16, dL + r * 272 + k8 * 16);
    }
}
template <int I>
__device__ void conv1(uint32_t dH, uint32_t dL, const float* __restrict__ X,
                      int nbase, int Nn) {
    for (int idx = threadIdx.x; idx < 512; idx += THREADS) {
        const int r = idx >> 3, b = idx & 7;
        const float* p = X + (size_t)min(nbase + r, Nn - 1) * 480 + 128 + 24 * b;
        float v[8];
#pragma unroll
        for (int q = 0; q < 8; q++) v[q] = __ldg(&p[I + 3 * q]);
        pack_sts8(v, dH + r * 144 + b * 16, dL + r * 144 + b * 16);
    }
}
template <int I>
__device__ void conv2(uint32_t dH, uint32_t dL, const float* __restrict__ X,
                      int nbase, int Nn) {
    for (int idx = threadIdx.x; idx < 256; idx += THREADS) {
        const int r = idx >> 2, b = idx & 3;
        const float* p = X + (size_t)min(nbase + r, Nn - 1) * 480 + 320 + 40 * b;
        float v[8];
#pragma unroll
        for (int q = 0; q < 8; q++) v[q] = __ldg(&p[I + 5 * q]);
        pack_sts8(v, dH + r * 80 + b * 16, dL + r * 80 + b * 16);
    }
}

template <int NTW>
__device__ __forceinline__ void zacc(float (&acc)[2][NTW][4]) {
#pragma unroll
    for (int m = 0; m < 2; m++)
#pragma unroll
        for (int j = 0; j < NTW; j++)
#pragma unroll
            for (int q = 0; q < 4; q++) acc[m][j][q] = 0.0f;
}

template <int KT, int NTW>
__device__ __forceinline__ void mma_tile(uint32_t uAH, uint32_t uAL, uint32_t uBH,
                                         uint32_t uBL, int Kpad, int rowBase, int n8Base,
                                         int lane, float (&acc)[2][NTW][4]) {
    const int ar  = rowBase + (lane & 15);
    const int ak8 = (lane >> 4) * 8;
    const int bn  = lane & 7;
    const int bk8 = ((lane >> 3) & 1) * 8;
#pragma unroll 1
    for (int kt = 0; kt < KT; kt++) {
        const int kb = kt * 16;
        uint32_t Ah[2][4], Al[2][4];
#pragma unroll
        for (int m = 0; m < 2; m++) {
            const uint32_t off = (uint32_t)(((ar + m * 16) * Kpad + kb + ak8) * 2);
            ldm_x4(Ah[m], uAH + off);
            ldm_x4(Al[m], uAL + off);
        }
#pragma unroll
        for (int j = 0; j < NTW; j++) {
            const uint32_t boff =
                (uint32_t)((((n8Base + j) * 8 + bn) * Kpad + kb + bk8) * 2);
            uint32_t Bh[2], Bl[2];
            ldm_x2(Bh, uBH + boff);
            ldm_x2(Bl, uBL + boff);
#pragma unroll
            for (int m = 0; m < 2; m++) {
                mma_bf(acc[m][j], Ah[m], Bh);
                mma_bf(acc[m][j], Ah[m], Bl);
                mma_bf(acc[m][j], Al[m], Bh);
            }
        }
    }
}

__device__ __forceinline__ void prep_w(const float* __restrict__ W, int K, int N,
                                       int Kpad, int base) {
    const int tot = K * N;
    for (int idx = blockIdx.x * blockDim.x + threadIdx.x; idx < tot;
         idx += gridDim.x * blockDim.x) {
        const int k = idx / N, n = idx - k * N;
        uint16_t h, l;
        split(__ldg(&W[idx]), h, l);
        g_wh[base + n * Kpad + k] = h;
        g_wl[base + n * Kpad + k] = l;
    }
}
__global__ void prep(const float* W1_0, const float* W1_1, const float* W1_2,
                     const float* W2_0, const float* W2_1, const float* W2_2) {
    prep_w(W1_0, 128, 672, 136, OFF10);
    prep_w(W1_1, 64, 192, 72, OFF11);
    prep_w(W1_2, 32, 96, 40, OFF12);
    for (int idx = blockIdx.x * blockDim.x + threadIdx.x; idx < 384 * 128;
         idx += gridDim.x * blockDim.x) {
        const int k = idx / 128, n = idx - k * 128;
        const int kc = k >> 5, kk = k & 31;
        uint16_t h, l;
        split(__ldg(&W2_0[idx]), h, l);
        g_wh[OFF20 + kc * 5120 + n * 40 + kk] = h;
        g_wl[OFF20 + kc * 5120 + n * 40 + kk] = l;
    }
    for (int idx = blockIdx.x * blockDim.x + threadIdx.x; idx < 192 * 64;
         idx += gridDim.x * blockDim.x) {
        const int k = idx / 64, n = idx - k * 64;
        const int kc = k / 48, kk = k - kc * 48;
        uint16_t h, l;
        split(__ldg(&W2_1[idx]), h, l);
        g_wh[OFF21 + kc * 3584 + n * 56 + kk] = h;
        g_wl[OFF21 + kc * 3584 + n * 56 + kk] = l;
    }
    prep_w(W2_2, 96, 32, 104, OFF22);
}

__global__ void __launch_bounds__(THREADS, 3)
ffn_main(const float* __restrict__ X, const float* __restrict__ attr,
         const float* __restrict__ b1, const float* __restrict__ b2,
         float* __restrict__ out, int Nn) {
    extern __shared__ char smem[];
    float* sAttr = (float*)smem;
    const uint32_t sb = s2u(smem);
    const int tid = threadIdx.x, lane = tid & 31, w = tid >> 5;
    const int g = lane >> 2, t2 = lane & 3;
    const int mt = w >> 2, nt = w & 3;
    const size_t cta = blockIdx.x;
    const int nbase = (int)cta * 64;
    uint16_t* scH = g_scH + cta * 25088;
    uint16_t* scL = g_scL + cta * 25088;
    float* gate = g_gate + cta * 18432;

    const float I10 = 0.08838834764831843f, I11 = 0.125f, I12 = 0.17677669529663687f;
    const float I20 = 0.05103103630798288f, I21 = 0.07216878364870323f,
                I22 = 0.10206207261596577f;

    // ===== P0: h0 = x0 @ W1_0 (10 N-chunks of 64 + tail 32) =====
    cpy2(sb + 35328, sb + 52736, g_wh + OFF10, g_wl + OFF10, 8704);
    CP_COMMIT();
    if (tid < 64) sAttr[tid] = attr[min(nbase + tid, Nn - 1)];
    conv_seg0(sb + 512, sb + 17920, X, nbase, Nn);
    for (int ch = 0; ch < 11; ch++) {
        CP_WAIT0();
        __syncthreads();
        if (ch < 10) {
            float acc[2][2][4];
            zacc<2>(acc);
            mma_tile<8, 2>(sb + 512, sb + 17920, sb + 35328, sb + 52736, 136,
                           mt * 32, nt * 2, lane, acc);
            __syncthreads();
            if (ch < 9)
                cpy2(sb + 35328, sb + 52736, g_wh + OFF10 + (ch + 1) * 8704,
                     g_wl + OFF10 + (ch + 1) * 8704, 8704);
            else
                cpy2(sb + 35328, sb + 52736, g_wh + OFF10 + 87040,
                     g_wl + OFF10 + 87040, 4352);
            CP_COMMIT();
#pragma unroll
            for (int m = 0; m < 2; m++) {
                const int r0 = mt * 32 + m * 16 + g;
#pragma unroll
                for (int j = 0; j < 2; j++) {
                    const int gc = ch * 64 + (nt * 2 + j) * 8 + t2 * 2;
                    const float bb0 = __ldg(&b1[gc]), bb1 = __ldg(&b1[gc + 1]);
#pragma unroll
                    for (int h2 = 0; h2 < 2; h2++) {
                        const int r = r0 + h2 * 8;
                        const float a = sAttr[r] * I10;
                        float x0 = acc[m][j][h2 * 2] * a + bb0;
                        float x1 = acc[m][j][h2 * 2 + 1] * a + bb1;
                        const float s0 = 1.0f / (1.0f + __expf(-x0));
                        const float s1 = 1.0f / (1.0f + __expf(-x1));
                        if (gc < 384)
                            st_pair(scH, scL, r * 392 + gc, x0 * s0, x1 * s1);
                        else
                            *reinterpret_cast<float2*>(gate + r * 288 + gc - 384) =
                                make_float2(s0, s1);
                    }
                }
            }
        } else {
            float acc[2][1][4];
            zacc<1>(acc);
            mma_tile<8, 1>(sb + 512, sb + 17920, sb + 35328, sb + 52736, 136,
                           mt * 32, nt, lane, acc);
            __syncthreads();
            cpy_sc32(sb + 512, sb + 5632, scH, scL, 0);
            cpy2(sb + 20992, sb + 31232, g_wh + OFF20, g_wl + OFF20, 5120);
            CP_COMMIT();
#pragma unroll
            for (int m = 0; m < 2; m++) {
                const int r0 = mt * 32 + m * 16 + g;
                const int gc = 640 + nt * 8 + t2 * 2;
                const float bb0 = __ldg(&b1[gc]), bb1 = __ldg(&b1[gc + 1]);
#pragma unroll
                for (int h2 = 0; h2 < 2; h2++) {
                    const int r = r0 + h2 * 8;
                    const float a = sAttr[r] * I10;
                    const float x0 = acc[m][0][h2 * 2] * a + bb0;
                    const float x1 = acc[m][0][h2 * 2 + 1] * a + bb1;
                    *reinterpret_cast<float2*>(gate + r * 288 + gc - 384) =
                        make_float2(1.0f / (1.0f + __expf(-x0)),
                                    1.0f / (1.0f + __expf(-x1)));
                }
            }
        }
    }

    // ===== P1: out0 = scalars @ W2_0 (12 K-chunks of 32, double-buffered) =====
    {
        const uint32_t aH[2] = {sb + 512, sb + 10752};
        const uint32_t aL[2] = {sb + 5632, sb + 15872};
        const uint32_t bH[2] = {sb + 20992, sb + 41472};
        const uint32_t bL[2] = {sb + 31232, sb + 51712};
        float acc[2][4][4];
        zacc<4>(acc);
        for (int kc = 0; kc < 12; kc++) {
            const int s = kc & 1;
            if (kc < 11) {
                cpy_sc32(aH[1 - s], aL[1 - s], scH, scL, (kc + 1) * 32);
                cpy2(bH[1 - s], bL[1 - s], g_wh + OFF20 + (kc + 1) * 5120,
                     g_wl + OFF20 + (kc + 1) * 5120, 5120);
                CP_COMMIT();
                CP_WAIT1();
            } else {
                CP_WAIT0();
            }
            __syncthreads();
            mma_tile<2, 4>(aH[s], aL[s], bH[s], bL[s], 40, mt * 32, nt * 4, lane, acc);
            __syncthreads();
        }
        cpy2(sb + 18944, sb + 25856, g_wh + OFF11, g_wl + OFF11, 3456);
        CP_COMMIT();
        cpy2(sb + 47104, sb + 54272, g_wh + OFF21, g_wl + OFF21, 3584);
        CP_COMMIT();
        conv1<0>(sb + 512, sb + 9728, X, nbase, Nn);
#pragma unroll
        for (int m = 0; m < 2; m++) {
            const int r0 = mt * 32 + m * 16 + g;
#pragma unroll
            for (int j = 0; j < 4; j++) {
                const int c = (nt * 4 + j) * 8 + t2 * 2;
                const float bb0 = __ldg(&b2[c]), bb1 = __ldg(&b2[c + 1]);
#pragma unroll
                for (int h2 = 0; h2 < 2; h2++) {
                    const int r = r0 + h2 * 8, node = nbase + r;
                    if (node < Nn) {
                        const float a = sAttr[r] * I20;
                        *reinterpret_cast<float2*>(out + (size_t)node * 480 + c) =
                            make_float2(acc[m][j][h2 * 2] * a + bb0,
                                        acc[m][j][h2 * 2 + 1] * a + bb1);
                    }
                }
            }
        }
    }

    // ===== P2: mid1_i -> out1_i fused, 4 K-chunks of 48 (i=0..2) =====
    {
        uint16_t* mH = (uint16_t*)(smem + 32768);
        uint16_t* mL = (uint16_t*)(smem + 39936);
        for (int i = 0; i < 3; i++) {
            float acc2[2][2][4];
            zacc<2>(acc2);
            for (int kc = 0; kc < 4; kc++) {
                CP_WAIT1();
                __syncthreads();
                float accA[2][1][4], accB[2][1][4];
                zacc<1>(accA);
                mma_tile<4, 1>(sb + 512, sb + 9728, sb + 18944, sb + 25856, 72,
                               (w / 6) * 32, w % 6, lane, accA);
                if (w < 4) {
                    zacc<1>(accB);
                    mma_tile<4, 1>(sb + 512, sb + 9728, sb + 18944, sb + 25856, 72,
                                   32, w + 2, lane, accB);
                }
                __syncthreads();
                if (kc < 3)
                    cpy2(sb + 18944, sb + 25856, g_wh + OFF11 + (kc + 1) * 3456,
                         g_wl + OFF11 + (kc + 1) * 3456, 3456);
                else if (i < 2)
                    cpy2(sb + 18944, sb + 25856, g_wh + OFF11, g_wl + OFF11, 3456);
                else
                    cpy2(sb + 10752, sb + 18432, g_wh + OFF12, g_wl + OFF12, 3840);
                CP_COMMIT();
                {
                    const int mtA = (w / 6), n8A = w % 6;
#pragma unroll
                    for (int m = 0; m < 2; m++) {
                        const int r0 = mtA * 32 + m * 16 + g;
                        const int c = n8A * 8 + t2 * 2;
#pragma unroll
                        for (int h2 = 0; h2 < 2; h2++) {
                            const int r = r0 + h2 * 8;
                            const float a = sAttr[r] * I11;
                            const float2 gg = *reinterpret_cast<const float2*>(
                                gate + r * 288 + kc * 48 + c);
                            st_pair(mH, mL, r * 56 + c,
                                    accA[m][0][h2 * 2] * a * gg.x,
                                    accA[m][0][h2 * 2 + 1] * a * gg.y);
                        }
                    }
                    if (w < 4) {
                        const int c = (w + 2) * 8 + t2 * 2;
#pragma unroll
                        for (int m = 0; m < 2; m++) {
                            const int r0 = 32 + m * 16 + g;
#pragma unroll
                            for (int h2 = 0; h2 < 2; h2++) {
                                const int r = r0 + h2 * 8;
                                const float a = sAttr[r] * I11;
                                const float2 gg = *reinterpret_cast<const float2*>(
                                    gate + r * 288 + kc * 48 + c);
                                st_pair(mH, mL, r * 56 + c,
                                        accB[m][0][h2 * 2] * a * gg.x,
                                        accB[m][0][h2 * 2 + 1] * a * gg.y);
                            }
                        }
                    }
                }
                if (kc == 3) {
                    if (i == 0)      conv1<1>(sb + 512, sb + 9728, X, nbase, Nn);
                    else if (i == 1) conv1<2>(sb + 512, sb + 9728, X, nbase, Nn);
                    else             conv2<0>(sb + 512, sb + 5632, X, nbase, Nn);
                }
                CP_WAIT1();
                __syncthreads();
                mma_tile<3, 2>(sb + 32768, sb + 39936, sb + 47104, sb + 54272, 56,
                               mt * 32, nt * 2, lane, acc2);
                __syncthreads();   // FIX: all warps done reading W2_1 before overwrite
                if (kc < 3)
                    cpy2(sb + 47104, sb + 54272, g_wh + OFF21 + (kc + 1) * 3584,
                         g_wl + OFF21 + (kc + 1) * 3584, 3584);
                else if (i < 2)
                    cpy2(sb + 47104, sb + 54272, g_wh + OFF21, g_wl + OFF21, 3584);
                CP_COMMIT();
            }
#pragma unroll
            for (int m = 0; m < 2; m++) {
                const int r0 = mt * 32 + m * 16 + g;
#pragma unroll
                for (int j = 0; j < 2; j++) {
                    const int c = (nt * 2 + j) * 8 + t2 * 2;
#pragma unroll
                    for (int h2 = 0; h2 < 2; h2++) {
                        const int r = r0 + h2 * 8, node = nbase + r;
                        if (node < Nn) {
                            const float a = sAttr[r] * I21;
                            out[(size_t)node * 480 + 128 + c * 3 + i] =
                                acc2[m][j][h2 * 2] * a;
                            out[(size_t)node * 480 + 128 + (c + 1) * 3 + i] =
                                acc2[m][j][h2 * 2 + 1] * a;
                        }
                    }
                }
            }
        }
    }

    // ===== P3: mid2_i -> out2_i fused (i=0..4) =====
    // X2 @512/5632; W1_2 @10752/18432; mid @26112/39424 (13312B each);
    // W2_2 @52736/59392
    {
        uint16_t* mH = (uint16_t*)(smem + 26112);
        uint16_t* mL = (uint16_t*)(smem + 39424);
        __syncthreads();   // FIX: all warps past final out1 mma before overwrite
        cpy2(sb + 52736, sb + 59392, g_wh + OFF22, g_wl + OFF22, 3328);
        CP_COMMIT();
        for (int i = 0; i < 5; i++) {
            if (i == 0) {
                CP_WAIT0();
                __syncthreads();
            }
            float acc[2][3][4];
            zacc<3>(acc);
            mma_tile<2, 3>(sb + 512, sb + 5632, sb + 10752, sb + 18432, 40,
                           mt * 32, nt * 3, lane, acc);
            __syncthreads();
#pragma unroll
            for (int m = 0; m < 2; m++) {
                const int r0 = mt * 32 + m * 16 + g;
#pragma unroll
                for (int j = 0; j < 3; j++) {
                    const int c = (nt * 3 + j) * 8 + t2 * 2;
#pragma unroll
                    for (int h2 = 0; h2 < 2; h2++) {
                        const int r = r0 + h2 * 8;
                        const float a = sAttr[r] * I12;
                        const float2 gg = *reinterpret_cast<const float2*>(
                            gate + r * 288 + 192 + c);
                        st_pair(mH, mL, r * 104 + c, acc[m][j][h2 * 2] * a * gg.x,
                                acc[m][j][h2 * 2 + 1] * a * gg.y);
                    }
                }
            }
            if (i == 0)      conv2<1>(sb + 512, sb + 5632, X, nbase, Nn);
            else if (i == 1) conv2<2>(sb + 512, sb + 5632, X, nbase, Nn);
            else if (i == 2) conv2<3>(sb + 512, sb + 5632, X, nbase, Nn);
            else if (i == 3) conv2<4>(sb + 512, sb + 5632, X, nbase, Nn);
            __syncthreads();
            float acc2[2][1][4];
            zacc<1>(acc2);
            mma_tile<6, 1>(sb + 26112, sb + 39424, sb + 52736, sb + 59392, 104,
                           mt * 32, nt, lane, acc2);
#pragma unroll
            for (int m = 0; m < 2; m++) {
                const int r0 = mt * 32 + m * 16 + g;
                const int c = nt * 8 + t2 * 2;
#pragma unroll
                for (int h2 = 0; h2 < 2; h2++) {
                    const int r = r0 + h2 * 8, node = nbase + r;
                    if (node < Nn) {
                        const float a = sAttr[r] * I22;
                        out[(size_t)node * 480 + 320 + c * 5 + i] =
                            acc2[m][0][h2 * 2] * a;
                        out[(size_t)node * 480 + 320 + (c + 1) * 5 + i] =
                            acc2[m][0][h2 * 2 + 1] * a;
                    }
                }
            }
            __syncthreads();
        }
    }
}

extern "C" void kernel_launch(void* const* d_in, const int* in_sizes, int n_in,
                              void* d_out, int out_size) {
    const float* X    = (const float*)d_in[0];
    const float* attr = (const float*)d_in[1];
    const float* W1_0 = (const float*)d_in[2];
    const float* W1_1 = (const float*)d_in[3];
    const float* W1_2 = (const float*)d_in[4];
    const float* b1   = (const float*)d_in[5];
    const float* W2_0 = (const float*)d_in[6];
    const float* W2_1 = (const float*)d_in[7];
    const float* W2_2 = (const float*)d_in[8];
    const float* b2   = (const float*)d_in[9];
    float* out = (float*)d_out;

    const int N = in_sizes[0] / 480;
    int nct = (N + 63) / 64;
    if (nct > MAXCTA) nct = MAXCTA;

    prep<<<160, 256>>>(W1_0, W1_1, W1_2, W2_0, W2_1, W2_2);
    cudaFuncSetAttribute(ffn_main, cudaFuncAttributeMaxDynamicSharedMemorySize, SM_TOT);
    ffn_main<<<nct, THREADS, SM_TOT>>>(X, attr, b1, b2, out, N);
}